// round 11
// baseline (speedup 1.0000x reference)
#include <cuda_runtime.h>
#include <cstdint>

// ---------------------------------------------------------------------------
// Problem constants: B=4, E=400000, N_NODES=50000, N_REL=500, D=64, D_LG=256,
// K_PER_VI=20, N_MEM=131072. Scratch via device globals (no allocation).
// ---------------------------------------------------------------------------
__device__ float g_hc[131072 * 64];   // tanh(hidden_con @ Wc + bc)
__device__ float g_hu[50000 * 64];    // tanh(hidden_uncon @ Wu + bu)

// ---------------- packed f32x2 helpers (sm_103a) ----------------
__device__ __forceinline__ void unpack2(unsigned long long u, float& x, float& y) {
    asm("mov.b64 {%0,%1}, %2;" : "=f"(x), "=f"(y) : "l"(u));
}
__device__ __forceinline__ unsigned long long dup2(float x) {
    unsigned long long u;
    asm("mov.b64 %0, {%1,%1};" : "=l"(u) : "f"(x));
    return u;
}
__device__ __forceinline__ void fma2(unsigned long long& d,
                                     unsigned long long a, unsigned long long b) {
    asm("fma.rn.f32x2 %0, %1, %2, %0;" : "+l"(d) : "l"(a), "l"(b));
}
__device__ __forceinline__ unsigned long long mul2(unsigned long long a,
                                                   unsigned long long b) {
    unsigned long long d;
    asm("mul.rn.f32x2 %0, %1, %2;" : "=l"(d) : "l"(a), "l"(b));
    return d;
}

__device__ __forceinline__ float tanh_fast(float x) {
    float e = __expf(-2.0f * fabsf(x));
    float t = (1.0f - e) / (1.0f + e);
    return copysignf(t, x);
}

// ---------------------------------------------------------------------------
// Projection v8 (unchanged from round 10, known ~75us): cp.async double-
// buffered pipeline for X and W; heavy hu (K=256) blocks first.
// ---------------------------------------------------------------------------
template <int K>
__device__ __forceinline__ void proj_tile_async(
    const float* __restrict__ X, const float* __restrict__ W,
    const float* __restrict__ bias, float* __restrict__ out,
    int rows, int bid, float* sm)
{
    constexpr int NC = K / 32;
    float* xbuf[2] = {sm, sm + 4608};
    float* wbuf[2] = {sm + 9216, sm + 11264};

    const int tid  = threadIdx.x;
    const int lane = tid & 31;
    const int warp = tid >> 5;
    const int cg   = lane >> 3;
    const int rp   = lane & 7;
    const int r0   = bid * 128;
    const int row0 = warp * 16 + rp;

    unsigned int xs[2], wsm[2];
    xs[0]  = (unsigned int)__cvta_generic_to_shared(xbuf[0]);
    xs[1]  = (unsigned int)__cvta_generic_to_shared(xbuf[1]);
    wsm[0] = (unsigned int)__cvta_generic_to_shared(wbuf[0]);
    wsm[1] = (unsigned int)__cvta_generic_to_shared(wbuf[1]);

    auto issue_chunk = [&](int c) {
        const int k0 = c * 32;
        const unsigned int xdst = xs[c & 1];
        const unsigned int wdst = wsm[c & 1];
#pragma unroll
        for (int p = 0; p < 4; p++) {
            int idx = tid + p * 256;
            int row = idx >> 3, c16 = idx & 7;
            int grow = r0 + row;
            int sz = (grow < rows) ? 16 : 0;
            if (grow >= rows) grow = rows - 1;
            const float* src = X + (size_t)grow * K + k0 + 4 * c16;
            unsigned int dst = xdst + (unsigned int)(row * 36 + 4 * c16) * 4u;
            asm volatile("cp.async.ca.shared.global [%0], [%1], 16, %2;"
                         :: "r"(dst), "l"(src), "r"(sz) : "memory");
        }
#pragma unroll
        for (int p = 0; p < 2; p++) {
            int idx = tid + p * 256;
            const float* src = W + (size_t)k0 * 64 + 4 * idx;
            unsigned int dst = wdst + (unsigned int)(4 * idx) * 4u;
            asm volatile("cp.async.ca.shared.global [%0], [%1], 16;"
                         :: "r"(dst), "l"(src) : "memory");
        }
        asm volatile("cp.async.commit_group;" ::: "memory");
    };

    unsigned long long acc[2][8];
#pragma unroll
    for (int r = 0; r < 2; r++)
#pragma unroll
        for (int j = 0; j < 8; j++) acc[r][j] = 0ull;

    issue_chunk(0);

#pragma unroll
    for (int c = 0; c < NC; c++) {
        if (c + 1 < NC) {
            issue_chunk(c + 1);
            asm volatile("cp.async.wait_group 1;" ::: "memory");
        } else {
            asm volatile("cp.async.wait_group 0;" ::: "memory");
        }
        __syncthreads();

        const float* xb = xbuf[c & 1] + (size_t)row0 * 36;
        const float* wb = wbuf[c & 1] + cg * 16;
#pragma unroll 8
        for (int kk = 0; kk < 32; kk++) {
            unsigned long long xq0 = dup2(xb[kk]);
            unsigned long long xq1 = dup2(xb[8 * 36 + kk]);
            const ulonglong2* wp =
                reinterpret_cast<const ulonglong2*>(wb + (size_t)kk * 64);
            ulonglong2 wA = wp[0], wB = wp[1], wC = wp[2], wD = wp[3];
            unsigned long long wv[8] = {wA.x, wA.y, wB.x, wB.y,
                                        wC.x, wC.y, wD.x, wD.y};
#pragma unroll
            for (int j = 0; j < 8; j++) fma2(acc[0][j], xq0, wv[j]);
#pragma unroll
            for (int j = 0; j < 8; j++) fma2(acc[1][j], xq1, wv[j]);
        }
        __syncthreads();
    }

    float bv[16];
#pragma unroll
    for (int j = 0; j < 16; j++) bv[j] = __ldg(&bias[cg * 16 + j]);
#pragma unroll
    for (int r = 0; r < 2; r++) {
        int row = row0 + 8 * r;
        float* dst = &sm[(size_t)row * 68 + cg * 16];
#pragma unroll
        for (int j = 0; j < 8; j++) {
            float a, b;
            unpack2(acc[r][j], a, b);
            *reinterpret_cast<float2*>(dst + 2 * j) =
                make_float2(tanh_fast(a + bv[2 * j]), tanh_fast(b + bv[2 * j + 1]));
        }
    }
    __syncthreads();
#pragma unroll
    for (int i = 0; i < 8; i++) {
        int idx = tid + i * 256;
        int row = idx >> 4, c4 = idx & 15;
        if (r0 + row < rows)
            *reinterpret_cast<float4*>(&out[(size_t)(r0 + row) * 64 + 4 * c4]) =
                *reinterpret_cast<const float4*>(&sm[(size_t)row * 68 + 4 * c4]);
    }
}

__global__ void __launch_bounds__(256, 3) proj_both_kernel(
    const float* __restrict__ Xc, const float* __restrict__ Wc,
    const float* __restrict__ bc, int rows_c,
    const float* __restrict__ Xu, const float* __restrict__ Wu,
    const float* __restrict__ bu, int rows_u, int nb_u)
{
    extern __shared__ float sm[];
    if ((int)blockIdx.x < nb_u) {
        proj_tile_async<256>(Xu, Wu, bu, g_hu, rows_u, blockIdx.x, sm);
    } else {
        proj_tile_async<64>(Xc, Wc, bc, g_hc, rows_c, blockIdx.x - nb_u, sm);
    }
}

// ---------------------------------------------------------------------------
// Edge kernel v5: half-warp float4 gathers + packed f32x2 logit math.
// 2 segments per 320-thread block, 5 warps/segment, 4 edges/warp processed as
// 2 half-warp pairs: lanes 0-15 own edge 2p, lanes 16-31 own edge 2p+1, each
// lane covers dims 4q..4q+3 (q = lane&15). One LDG.128 covers two edges' rows
// (8 gather instrs vs 17), and the c3/c4/o chain runs in fma.rn.f32x2.
// ---------------------------------------------------------------------------
__global__ void __launch_bounds__(320, 3) edge_kernel(
    const float* __restrict__ natt, const int* __restrict__ edges,
    const float* __restrict__ edges_y, const float* __restrict__ rel_table,
    const float* __restrict__ ws, const float* __restrict__ fb,
    const float* __restrict__ out_w,
    float* __restrict__ out, int n_nodes)
{
    __shared__ __align__(16) float s_w[640];   // ws[512] | fb[64] | ow[64]
    __shared__ float s_logit[2][20];

    const int tid   = threadIdx.x;
    const int wid   = tid >> 5;            // 0..9
    const int lane  = tid & 31;
    const int seg_l = wid / 5;             // 0..1
    const int wis   = wid - seg_l * 5;     // 0..4
    const int hw    = lane >> 4;           // half-warp: 0 or 1
    const int q     = lane & 15;           // dim quad: dims 4q..4q+3

    const long long e_base = (long long)blockIdx.x * 40 + seg_l * 20 + wis * 4;

    // lanes 0..7 load the 8 int4 of this warp's 4 edges (coalesced 128B)
    int4 a = make_int4(0, 0, 0, 0);
    if (lane < 8)
        a = __ldg(&reinterpret_cast<const int4*>(edges)[2 * e_base + lane]);

    const int eg = __shfl_sync(0xFFFFFFFFu, a.x, 0);
    const int vi = __shfl_sync(0xFFFFFFFFu, a.y, 0);
    // per-lane edge for pair 0 is hw, for pair 1 is 2+hw
    const int vjA   = __shfl_sync(0xFFFFFFFFu, a.z, 2 * hw);
    const int relA  = __shfl_sync(0xFFFFFFFFu, a.w, 2 * hw);
    const int e2viA = __shfl_sync(0xFFFFFFFFu, a.z, 2 * hw + 1);
    const int e2vjA = __shfl_sync(0xFFFFFFFFu, a.w, 2 * hw + 1);
    const int vjB   = __shfl_sync(0xFFFFFFFFu, a.z, 2 * (2 + hw));
    const int relB  = __shfl_sync(0xFFFFFFFFu, a.w, 2 * (2 + hw));
    const int e2viB = __shfl_sync(0xFFFFFFFFu, a.z, 2 * (2 + hw) + 1);
    const int e2vjB = __shfl_sync(0xFFFFFFFFu, a.w, 2 * (2 + hw) + 1);
    // vj for the final atomic (lanes 0..3 handle edges 0..3)
    const int vjL   = __shfl_sync(0xFFFFFFFFu, a.z, 2 * (lane & 3));

    // stage weights once per block (640 floats over 320 threads)
    {
        int i = tid;
        s_w[i] = (i < 512) ? __ldg(&ws[i])
                           : (i < 576 ? __ldg(&fb[i - 512]) : __ldg(&out_w[i - 576]));
        int i2 = tid + 320;
        s_w[i2] = (i2 < 512) ? __ldg(&ws[i2])
                             : (i2 < 576 ? __ldg(&fb[i2 - 512]) : __ldg(&out_w[i2 - 576]));
    }

    // front-batched gathers: 8 LDG.128 (each covers 2 edges' rows) + f1 + scalars
    const int d4 = 4 * q;
    const ulonglong2 f0A = __ldg(reinterpret_cast<const ulonglong2*>(&g_hc[(size_t)e2viA * 64 + d4]));
    const ulonglong2 f3A = __ldg(reinterpret_cast<const ulonglong2*>(&g_hc[(size_t)e2vjA * 64 + d4]));
    const ulonglong2 f4A = __ldg(reinterpret_cast<const ulonglong2*>(&g_hu[(size_t)vjA  * 64 + d4]));
    const ulonglong2 f2A = __ldg(reinterpret_cast<const ulonglong2*>(&rel_table[(size_t)relA * 64 + d4]));
    const ulonglong2 f0B = __ldg(reinterpret_cast<const ulonglong2*>(&g_hc[(size_t)e2viB * 64 + d4]));
    const ulonglong2 f3B = __ldg(reinterpret_cast<const ulonglong2*>(&g_hc[(size_t)e2vjB * 64 + d4]));
    const ulonglong2 f4B = __ldg(reinterpret_cast<const ulonglong2*>(&g_hu[(size_t)vjB  * 64 + d4]));
    const ulonglong2 f2B = __ldg(reinterpret_cast<const ulonglong2*>(&rel_table[(size_t)relB * 64 + d4]));
    const ulonglong2 f1  = __ldg(reinterpret_cast<const ulonglong2*>(&g_hu[(size_t)vi * 64 + d4]));
    const float att = __ldg(&natt[(size_t)eg * n_nodes + vi]);
    const float ey  = (lane < 4) ? __ldg(&edges_y[e_base + lane]) : 0.0f;

    __syncthreads();   // weights staged

    // packed weights at this lane's 4 dims
    const ulonglong2 w0 = *reinterpret_cast<const ulonglong2*>(&s_w[0 * 64 + d4]);
    const ulonglong2 w1 = *reinterpret_cast<const ulonglong2*>(&s_w[1 * 64 + d4]);
    const ulonglong2 w2 = *reinterpret_cast<const ulonglong2*>(&s_w[2 * 64 + d4]);
    const ulonglong2 w3 = *reinterpret_cast<const ulonglong2*>(&s_w[3 * 64 + d4]);
    const ulonglong2 w4 = *reinterpret_cast<const ulonglong2*>(&s_w[4 * 64 + d4]);
    const ulonglong2 w5 = *reinterpret_cast<const ulonglong2*>(&s_w[5 * 64 + d4]);
    const ulonglong2 w6 = *reinterpret_cast<const ulonglong2*>(&s_w[6 * 64 + d4]);
    const ulonglong2 w7 = *reinterpret_cast<const ulonglong2*>(&s_w[7 * 64 + d4]);
    const ulonglong2 vb = *reinterpret_cast<const ulonglong2*>(&s_w[512 + d4]);
    float owv[4];
    owv[0] = s_w[576 + d4];     owv[1] = s_w[576 + d4 + 1];
    owv[2] = s_w[576 + d4 + 2]; owv[3] = s_w[576 + d4 + 3];

    // f1-dependent terms (shared by all edges of the segment), packed:
    //   c3 = f0*w0 + (f0*f2)*w1 + f1*w4 + (f1*f2)*w5
    //   c4 = f0*w2 + (f0*f2)*w3 + f1*w6 + (f1*f2)*w7
    const unsigned long long h4lo = mul2(f1.x, w4.x), h4hi = mul2(f1.y, w4.y);
    const unsigned long long h5lo = mul2(f1.x, w5.x), h5hi = mul2(f1.y, w5.y);
    const unsigned long long h6lo = mul2(f1.x, w6.x), h6hi = mul2(f1.y, w6.y);
    const unsigned long long h7lo = mul2(f1.x, w7.x), h7hi = mul2(f1.y, w7.y);

    // packed logit partial for one edge (4 dims in 2 f32x2 lanes)
#define EDGE_PARTIAL(f0v, f2v, f3v, f4v, pout)                                   \
    {                                                                            \
        float p = 0.0f;                                                          \
        {   /* lo pair: dims 4q,4q+1 */                                          \
            unsigned long long a1 = mul2(f0v.x, f2v.x);                          \
            unsigned long long c3 = h4lo; fma2(c3, f2v.x, h5lo);                 \
            fma2(c3, a1, w1.x); fma2(c3, f0v.x, w0.x);                           \
            unsigned long long c4 = h6lo; fma2(c4, f2v.x, h7lo);                 \
            fma2(c4, a1, w3.x); fma2(c4, f0v.x, w2.x);                           \
            unsigned long long o = vb.x; fma2(o, f3v.x, c3); fma2(o, f4v.x, c4); \
            float ox, oy; unpack2(o, ox, oy);                                    \
            p = fmaf(fmaxf(ox, 0.0f), owv[0], p);                                \
            p = fmaf(fmaxf(oy, 0.0f), owv[1], p);                                \
        }                                                                        \
        {   /* hi pair: dims 4q+2,4q+3 */                                        \
            unsigned long long a1 = mul2(f0v.y, f2v.y);                          \
            unsigned long long c3 = h4hi; fma2(c3, f2v.y, h5hi);                 \
            fma2(c3, a1, w1.y); fma2(c3, f0v.y, w0.y);                           \
            unsigned long long c4 = h6hi; fma2(c4, f2v.y, h7hi);                 \
            fma2(c4, a1, w3.y); fma2(c4, f0v.y, w2.y);                           \
            unsigned long long o = vb.y; fma2(o, f3v.y, c3); fma2(o, f4v.y, c4); \
            float ox, oy; unpack2(o, ox, oy);                                    \
            p = fmaf(fmaxf(ox, 0.0f), owv[2], p);                                \
            p = fmaf(fmaxf(oy, 0.0f), owv[3], p);                                \
        }                                                                        \
        pout = p;                                                                \
    }

    float pA, pB;
    EDGE_PARTIAL(f0A, f2A, f3A, f4A, pA)
    EDGE_PARTIAL(f0B, f2B, f3B, f4B, pB)
#undef EDGE_PARTIAL

    // half-warp reduction (xor offsets < 16 stay within each half)
#pragma unroll
    for (int s = 8; s > 0; s >>= 1) {
        pA += __shfl_xor_sync(0xFFFFFFFFu, pA, s);
        pB += __shfl_xor_sync(0xFFFFFFFFu, pB, s);
    }
    if (q == 0) {
        s_logit[seg_l][wis * 4 + hw]     = pA;   // edges 0(hw=0), 1(hw=1)
        s_logit[seg_l][wis * 4 + 2 + hw] = pB;   // edges 2, 3
    }
    __syncthreads();

    // segment softmax (each warp redundantly for its own segment)
    float l = (lane < 20) ? s_logit[seg_l][lane] : -1e30f;
    float m = l;
#pragma unroll
    for (int s = 16; s > 0; s >>= 1) m = fmaxf(m, __shfl_xor_sync(0xFFFFFFFFu, m, s));
    float ev = (lane < 20) ? __expf(l - m) : 0.0f;
#pragma unroll
    for (int s = 16; s > 0; s >>= 1) ev += __shfl_xor_sync(0xFFFFFFFFu, ev, s);

    if (lane < 4) {
        float lg = s_logit[seg_l][wis * 4 + lane];
        float trans = __expf(lg - m) / ev;
        atomicAdd(&out[(size_t)eg * n_nodes + vjL], trans * att * ey);
    }
}

// ---------------------------------------------------------------------------
extern "C" void kernel_launch(void* const* d_in, const int* in_sizes, int n_in,
                              void* d_out, int out_size)
{
    const float* natt    = (const float*)d_in[0];
    const int*   edges   = (const int*)d_in[1];
    const float* edges_y = (const float*)d_in[2];
    const float* hu_in   = (const float*)d_in[3];   // [1, n_nodes, 256]
    const float* hc_in   = (const float*)d_in[4];   // [n_mem, 64]
    const float* Wc      = (const float*)d_in[5];
    const float* bc      = (const float*)d_in[6];
    const float* Wu      = (const float*)d_in[7];
    const float* bu      = (const float*)d_in[8];
    const float* rel_t   = (const float*)d_in[9];
    const float* ws      = (const float*)d_in[10];
    const float* fb      = (const float*)d_in[11];
    const float* ow      = (const float*)d_in[12];

    const int E       = in_sizes[2];
    const int n_nodes = in_sizes[3] / 256;
    const int n_mem   = in_sizes[4] / 64;
    const int n_seg   = E / 20;

    const int nb_c = (n_mem + 127) / 128;      // 1024
    const int nb_u = (n_nodes + 127) / 128;    // 391

    const int dyn_smem = 13312 * 4;            // 53,248 bytes
    cudaFuncSetAttribute(proj_both_kernel,
                         cudaFuncAttributeMaxDynamicSharedMemorySize, dyn_smem);
    cudaFuncSetAttribute(proj_both_kernel,
                         cudaFuncAttributePreferredSharedMemoryCarveout, 100);

    cudaMemsetAsync(d_out, 0, (size_t)out_size * sizeof(float));

    proj_both_kernel<<<nb_c + nb_u, 256, dyn_smem>>>(
        hc_in, Wc, bc, n_mem, hu_in, Wu, bu, n_nodes, nb_u);

    edge_kernel<<<n_seg / 2, 320>>>(natt, edges, edges_y, rel_t, ws, fb, ow,
                                    (float*)d_out, n_nodes);
}

// round 12
// speedup vs baseline: 1.0663x; 1.0663x over previous
#include <cuda_runtime.h>
#include <cstdint>

// ---------------------------------------------------------------------------
// Problem constants: B=4, E=400000, N_NODES=50000, N_REL=500, D=64, D_LG=256,
// K_PER_VI=20, N_MEM=131072. Scratch via device globals (no allocation).
// ---------------------------------------------------------------------------
__device__ float g_hc[131072 * 64];   // tanh(hidden_con @ Wc + bc)
__device__ float g_hu[50000 * 64];    // tanh(hidden_uncon @ Wu + bu)

// ---------------- packed f32x2 helpers (sm_103a) ----------------
__device__ __forceinline__ void unpack2(unsigned long long u, float& x, float& y) {
    asm("mov.b64 {%0,%1}, %2;" : "=f"(x), "=f"(y) : "l"(u));
}
__device__ __forceinline__ unsigned long long dup2(float x) {
    unsigned long long u;
    asm("mov.b64 %0, {%1,%1};" : "=l"(u) : "f"(x));
    return u;
}
__device__ __forceinline__ void fma2(unsigned long long& d,
                                     unsigned long long a, unsigned long long b) {
    asm("fma.rn.f32x2 %0, %1, %2, %0;" : "+l"(d) : "l"(a), "l"(b));
}

__device__ __forceinline__ float tanh_fast(float x) {
    float e = __expf(-2.0f * fabsf(x));
    float t = (1.0f - e) / (1.0f + e);
    return copysignf(t, x);
}

// ---------------------------------------------------------------------------
// Projection v8b: cp.async double-buffered pipeline (round-10 config) with
// explicit float4 x-loads in the inner loop (1 LDS.128 per 4 kk per row).
// out[row,0:64] = tanh(X[row,0:K] @ W[K,64] + bias); heavy hu blocks first.
// ---------------------------------------------------------------------------
template <int K>
__device__ __forceinline__ void proj_tile_async(
    const float* __restrict__ X, const float* __restrict__ W,
    const float* __restrict__ bias, float* __restrict__ out,
    int rows, int bid, float* sm)
{
    constexpr int NC = K / 32;
    float* xbuf[2] = {sm, sm + 4608};
    float* wbuf[2] = {sm + 9216, sm + 11264};

    const int tid  = threadIdx.x;
    const int lane = tid & 31;
    const int warp = tid >> 5;
    const int cg   = lane >> 3;
    const int rp   = lane & 7;
    const int r0   = bid * 128;
    const int row0 = warp * 16 + rp;

    unsigned int xs[2], wsm[2];
    xs[0]  = (unsigned int)__cvta_generic_to_shared(xbuf[0]);
    xs[1]  = (unsigned int)__cvta_generic_to_shared(xbuf[1]);
    wsm[0] = (unsigned int)__cvta_generic_to_shared(wbuf[0]);
    wsm[1] = (unsigned int)__cvta_generic_to_shared(wbuf[1]);

    auto issue_chunk = [&](int c) {
        const int k0 = c * 32;
        const unsigned int xdst = xs[c & 1];
        const unsigned int wdst = wsm[c & 1];
#pragma unroll
        for (int p = 0; p < 4; p++) {
            int idx = tid + p * 256;
            int row = idx >> 3, c16 = idx & 7;
            int grow = r0 + row;
            int sz = (grow < rows) ? 16 : 0;
            if (grow >= rows) grow = rows - 1;
            const float* src = X + (size_t)grow * K + k0 + 4 * c16;
            unsigned int dst = xdst + (unsigned int)(row * 36 + 4 * c16) * 4u;
            asm volatile("cp.async.ca.shared.global [%0], [%1], 16, %2;"
                         :: "r"(dst), "l"(src), "r"(sz) : "memory");
        }
#pragma unroll
        for (int p = 0; p < 2; p++) {
            int idx = tid + p * 256;
            const float* src = W + (size_t)k0 * 64 + 4 * idx;
            unsigned int dst = wdst + (unsigned int)(4 * idx) * 4u;
            asm volatile("cp.async.ca.shared.global [%0], [%1], 16;"
                         :: "r"(dst), "l"(src) : "memory");
        }
        asm volatile("cp.async.commit_group;" ::: "memory");
    };

    unsigned long long acc[2][8];
#pragma unroll
    for (int r = 0; r < 2; r++)
#pragma unroll
        for (int j = 0; j < 8; j++) acc[r][j] = 0ull;

    issue_chunk(0);

#pragma unroll
    for (int c = 0; c < NC; c++) {
        if (c + 1 < NC) {
            issue_chunk(c + 1);
            asm volatile("cp.async.wait_group 1;" ::: "memory");
        } else {
            asm volatile("cp.async.wait_group 0;" ::: "memory");
        }
        __syncthreads();

        const float4* xb0 = reinterpret_cast<const float4*>(
                                xbuf[c & 1] + (size_t)row0 * 36);
        const float4* xb1 = reinterpret_cast<const float4*>(
                                xbuf[c & 1] + (size_t)(row0 + 8) * 36);
        const float* wb = wbuf[c & 1] + cg * 16;
#pragma unroll
        for (int k4 = 0; k4 < 8; k4++) {
            float4 xq0 = xb0[k4];
            float4 xq1 = xb1[k4];
            const float x0[4] = {xq0.x, xq0.y, xq0.z, xq0.w};
            const float x1[4] = {xq1.x, xq1.y, xq1.z, xq1.w};
#pragma unroll
            for (int t = 0; t < 4; t++) {
                unsigned long long d0 = dup2(x0[t]);
                unsigned long long d1 = dup2(x1[t]);
                const ulonglong2* wp = reinterpret_cast<const ulonglong2*>(
                    wb + (size_t)(4 * k4 + t) * 64);
                ulonglong2 wA = wp[0], wB = wp[1], wC = wp[2], wD = wp[3];
                unsigned long long wv[8] = {wA.x, wA.y, wB.x, wB.y,
                                            wC.x, wC.y, wD.x, wD.y};
#pragma unroll
                for (int j = 0; j < 8; j++) fma2(acc[0][j], d0, wv[j]);
#pragma unroll
                for (int j = 0; j < 8; j++) fma2(acc[1][j], d1, wv[j]);
            }
        }
        __syncthreads();
    }

    // ---- epilogue: bias + tanh, stage to smem [128][68], coalesced stores --
    float bv[16];
#pragma unroll
    for (int j = 0; j < 16; j++) bv[j] = __ldg(&bias[cg * 16 + j]);
#pragma unroll
    for (int r = 0; r < 2; r++) {
        int row = row0 + 8 * r;
        float* dst = &sm[(size_t)row * 68 + cg * 16];
#pragma unroll
        for (int j = 0; j < 8; j++) {
            float a, b;
            unpack2(acc[r][j], a, b);
            *reinterpret_cast<float2*>(dst + 2 * j) =
                make_float2(tanh_fast(a + bv[2 * j]), tanh_fast(b + bv[2 * j + 1]));
        }
    }
    __syncthreads();
#pragma unroll
    for (int i = 0; i < 8; i++) {
        int idx = tid + i * 256;
        int row = idx >> 4, c4 = idx & 15;
        if (r0 + row < rows)
            *reinterpret_cast<float4*>(&out[(size_t)(r0 + row) * 64 + 4 * c4]) =
                *reinterpret_cast<const float4*>(&sm[(size_t)row * 68 + 4 * c4]);
    }
}

__global__ void __launch_bounds__(256, 3) proj_both_kernel(
    const float* __restrict__ Xc, const float* __restrict__ Wc,
    const float* __restrict__ bc, int rows_c,
    const float* __restrict__ Xu, const float* __restrict__ Wu,
    const float* __restrict__ bu, int rows_u, int nb_u)
{
    extern __shared__ float sm[];
    if ((int)blockIdx.x < nb_u) {
        proj_tile_async<256>(Xu, Wu, bu, g_hu, rows_u, blockIdx.x, sm);
    } else {
        proj_tile_async<64>(Xc, Wc, bc, g_hc, rows_c, blockIdx.x - nb_u, sm);
    }
}

// Tiny no-op kernel: shifts ncu's "-s 5 -c 1" capture point so launch #6 of
// the run is proj_both_kernel (replay = memset, proj, dummy, edge).
__global__ void capture_align_kernel() {}

// ---------------------------------------------------------------------------
// Edge kernel v4 (round-6/10 version, known 64us): 2 segments per 320-thread
// block, 5 warps/segment, 4 edges/warp. Weights staged in smem once per
// block; gathers front-batched; out_b dropped (softmax-invariant).
// ---------------------------------------------------------------------------
__global__ void __launch_bounds__(320, 3) edge_kernel(
    const float* __restrict__ natt, const int* __restrict__ edges,
    const float* __restrict__ edges_y, const float* __restrict__ rel_table,
    const float* __restrict__ ws, const float* __restrict__ fb,
    const float* __restrict__ out_w,
    float* __restrict__ out, int n_nodes)
{
    __shared__ __align__(16) float s_w[640];   // ws[512] | fb[64] | ow[64]
    __shared__ float s_logit[2][20];

    const int tid   = threadIdx.x;
    const int wid   = tid >> 5;            // 0..9
    const int lane  = tid & 31;
    const int seg_l = wid / 5;             // 0..1
    const int wis   = wid - seg_l * 5;     // 0..4

    const long long e_base = (long long)blockIdx.x * 40 + seg_l * 20 + wis * 4;

    int4 a = make_int4(0, 0, 0, 0);
    if (lane < 8)
        a = __ldg(&reinterpret_cast<const int4*>(edges)[2 * e_base + lane]);

    const int eg    = __shfl_sync(0xFFFFFFFFu, a.x, 0);
    const int vi    = __shfl_sync(0xFFFFFFFFu, a.y, 0);
    const int vj0   = __shfl_sync(0xFFFFFFFFu, a.z, 0);
    const int rel0  = __shfl_sync(0xFFFFFFFFu, a.w, 0);
    const int e2vi0 = __shfl_sync(0xFFFFFFFFu, a.z, 1);
    const int e2vj0 = __shfl_sync(0xFFFFFFFFu, a.w, 1);
    const int vj1   = __shfl_sync(0xFFFFFFFFu, a.z, 2);
    const int rel1  = __shfl_sync(0xFFFFFFFFu, a.w, 2);
    const int e2vi1 = __shfl_sync(0xFFFFFFFFu, a.z, 3);
    const int e2vj1 = __shfl_sync(0xFFFFFFFFu, a.w, 3);
    const int vj2   = __shfl_sync(0xFFFFFFFFu, a.z, 4);
    const int rel2  = __shfl_sync(0xFFFFFFFFu, a.w, 4);
    const int e2vi2 = __shfl_sync(0xFFFFFFFFu, a.z, 5);
    const int e2vj2 = __shfl_sync(0xFFFFFFFFu, a.w, 5);
    const int vj3   = __shfl_sync(0xFFFFFFFFu, a.z, 6);
    const int rel3  = __shfl_sync(0xFFFFFFFFu, a.w, 6);
    const int e2vi3 = __shfl_sync(0xFFFFFFFFu, a.z, 7);
    const int e2vj3 = __shfl_sync(0xFFFFFFFFu, a.w, 7);
    const int vjL   = __shfl_sync(0xFFFFFFFFu, a.z, 2 * (lane & 3));

    {
        int i = tid;
        s_w[i] = (i < 512) ? __ldg(&ws[i])
                           : (i < 576 ? __ldg(&fb[i - 512]) : __ldg(&out_w[i - 576]));
        int i2 = tid + 320;
        s_w[i2] = (i2 < 512) ? __ldg(&ws[i2])
                             : (i2 < 576 ? __ldg(&fb[i2 - 512]) : __ldg(&out_w[i2 - 576]));
    }

    const int d = 2 * lane;
    const float2 f0a = __ldg(reinterpret_cast<const float2*>(&g_hc[(size_t)e2vi0 * 64 + d]));
    const float2 f0b = __ldg(reinterpret_cast<const float2*>(&g_hc[(size_t)e2vi1 * 64 + d]));
    const float2 f0c = __ldg(reinterpret_cast<const float2*>(&g_hc[(size_t)e2vi2 * 64 + d]));
    const float2 f0d = __ldg(reinterpret_cast<const float2*>(&g_hc[(size_t)e2vi3 * 64 + d]));
    const float2 f3a = __ldg(reinterpret_cast<const float2*>(&g_hc[(size_t)e2vj0 * 64 + d]));
    const float2 f3b = __ldg(reinterpret_cast<const float2*>(&g_hc[(size_t)e2vj1 * 64 + d]));
    const float2 f3c = __ldg(reinterpret_cast<const float2*>(&g_hc[(size_t)e2vj2 * 64 + d]));
    const float2 f3d = __ldg(reinterpret_cast<const float2*>(&g_hc[(size_t)e2vj3 * 64 + d]));
    const float2 f4a = __ldg(reinterpret_cast<const float2*>(&g_hu[(size_t)vj0 * 64 + d]));
    const float2 f4b = __ldg(reinterpret_cast<const float2*>(&g_hu[(size_t)vj1 * 64 + d]));
    const float2 f4c = __ldg(reinterpret_cast<const float2*>(&g_hu[(size_t)vj2 * 64 + d]));
    const float2 f4d = __ldg(reinterpret_cast<const float2*>(&g_hu[(size_t)vj3 * 64 + d]));
    const float2 f2a = __ldg(reinterpret_cast<const float2*>(&rel_table[(size_t)rel0 * 64 + d]));
    const float2 f2b = __ldg(reinterpret_cast<const float2*>(&rel_table[(size_t)rel1 * 64 + d]));
    const float2 f2c = __ldg(reinterpret_cast<const float2*>(&rel_table[(size_t)rel2 * 64 + d]));
    const float2 f2d = __ldg(reinterpret_cast<const float2*>(&rel_table[(size_t)rel3 * 64 + d]));
    const float2 f1  = __ldg(reinterpret_cast<const float2*>(&g_hu[(size_t)vi * 64 + d]));
    const float att  = __ldg(&natt[(size_t)eg * n_nodes + vi]);
    const float ey   = (lane < 4) ? __ldg(&edges_y[e_base + lane]) : 0.0f;

    __syncthreads();

    const float2 w0 = *reinterpret_cast<const float2*>(&s_w[0 * 64 + d]);
    const float2 w1 = *reinterpret_cast<const float2*>(&s_w[1 * 64 + d]);
    const float2 w2 = *reinterpret_cast<const float2*>(&s_w[2 * 64 + d]);
    const float2 w3 = *reinterpret_cast<const float2*>(&s_w[3 * 64 + d]);
    const float2 w4 = *reinterpret_cast<const float2*>(&s_w[4 * 64 + d]);
    const float2 w5 = *reinterpret_cast<const float2*>(&s_w[5 * 64 + d]);
    const float2 w6 = *reinterpret_cast<const float2*>(&s_w[6 * 64 + d]);
    const float2 w7 = *reinterpret_cast<const float2*>(&s_w[7 * 64 + d]);
    const float2 vb = *reinterpret_cast<const float2*>(&s_w[512 + d]);
    const float2 ow = *reinterpret_cast<const float2*>(&s_w[576 + d]);

    const float h4x = f1.x * w4.x, h4y = f1.y * w4.y;
    const float h5x = f1.x * w5.x, h5y = f1.y * w5.y;
    const float h6x = f1.x * w6.x, h6y = f1.y * w6.y;
    const float h7x = f1.x * w7.x, h7y = f1.y * w7.y;

#define EDGE_LOGIT(f0v, f2v, f3v, f4v, lout)                                     \
    {                                                                            \
        float a1x = f0v.x * f2v.x, a1y = f0v.y * f2v.y;                          \
        float c3x = fmaf(f0v.x, w0.x, fmaf(a1x, w1.x, fmaf(f2v.x, h5x, h4x)));   \
        float c3y = fmaf(f0v.y, w0.y, fmaf(a1y, w1.y, fmaf(f2v.y, h5y, h4y)));   \
        float c4x = fmaf(f0v.x, w2.x, fmaf(a1x, w3.x, fmaf(f2v.x, h7x, h6x)));   \
        float c4y = fmaf(f0v.y, w2.y, fmaf(a1y, w3.y, fmaf(f2v.y, h7y, h6y)));   \
        float oxv = fmaf(f3v.x, c3x, fmaf(f4v.x, c4x, vb.x));                    \
        float oyv = fmaf(f3v.y, c3y, fmaf(f4v.y, c4y, vb.y));                    \
        lout = fmaf(fmaxf(oxv, 0.0f), ow.x, fmaxf(oyv, 0.0f) * ow.y);            \
    }

    float l0, l1, l2, l3;
    EDGE_LOGIT(f0a, f2a, f3a, f4a, l0)
    EDGE_LOGIT(f0b, f2b, f3b, f4b, l1)
    EDGE_LOGIT(f0c, f2c, f3c, f4c, l2)
    EDGE_LOGIT(f0d, f2d, f3d, f4d, l3)
#undef EDGE_LOGIT

#pragma unroll
    for (int s = 16; s > 0; s >>= 1) {
        l0 += __shfl_xor_sync(0xFFFFFFFFu, l0, s);
        l1 += __shfl_xor_sync(0xFFFFFFFFu, l1, s);
        l2 += __shfl_xor_sync(0xFFFFFFFFu, l2, s);
        l3 += __shfl_xor_sync(0xFFFFFFFFu, l3, s);
    }
    if (lane == 0) {
        s_logit[seg_l][wis * 4 + 0] = l0;
        s_logit[seg_l][wis * 4 + 1] = l1;
        s_logit[seg_l][wis * 4 + 2] = l2;
        s_logit[seg_l][wis * 4 + 3] = l3;
    }
    __syncthreads();

    float l = (lane < 20) ? s_logit[seg_l][lane] : -1e30f;
    float m = l;
#pragma unroll
    for (int s = 16; s > 0; s >>= 1) m = fmaxf(m, __shfl_xor_sync(0xFFFFFFFFu, m, s));
    float ev = (lane < 20) ? __expf(l - m) : 0.0f;
#pragma unroll
    for (int s = 16; s > 0; s >>= 1) ev += __shfl_xor_sync(0xFFFFFFFFu, ev, s);

    if (lane < 4) {
        float lg = s_logit[seg_l][wis * 4 + lane];
        float trans = __expf(lg - m) / ev;
        atomicAdd(&out[(size_t)eg * n_nodes + vjL], trans * att * ey);
    }
}

// ---------------------------------------------------------------------------
extern "C" void kernel_launch(void* const* d_in, const int* in_sizes, int n_in,
                              void* d_out, int out_size)
{
    const float* natt    = (const float*)d_in[0];
    const int*   edges   = (const int*)d_in[1];
    const float* edges_y = (const float*)d_in[2];
    const float* hu_in   = (const float*)d_in[3];   // [1, n_nodes, 256]
    const float* hc_in   = (const float*)d_in[4];   // [n_mem, 64]
    const float* Wc      = (const float*)d_in[5];
    const float* bc      = (const float*)d_in[6];
    const float* Wu      = (const float*)d_in[7];
    const float* bu      = (const float*)d_in[8];
    const float* rel_t   = (const float*)d_in[9];
    const float* ws      = (const float*)d_in[10];
    const float* fb      = (const float*)d_in[11];
    const float* ow      = (const float*)d_in[12];

    const int E       = in_sizes[2];
    const int n_nodes = in_sizes[3] / 256;
    const int n_mem   = in_sizes[4] / 64;
    const int n_seg   = E / 20;

    const int nb_c = (n_mem + 127) / 128;      // 1024
    const int nb_u = (n_nodes + 127) / 128;    // 391

    const int dyn_smem = 13312 * 4;            // 53,248 bytes
    cudaFuncSetAttribute(proj_both_kernel,
                         cudaFuncAttributeMaxDynamicSharedMemorySize, dyn_smem);
    cudaFuncSetAttribute(proj_both_kernel,
                         cudaFuncAttributePreferredSharedMemoryCarveout, 100);

    cudaMemsetAsync(d_out, 0, (size_t)out_size * sizeof(float));     // launch 1

    proj_both_kernel<<<nb_c + nb_u, 256, dyn_smem>>>(                // launch 2
        hc_in, Wc, bc, n_mem, hu_in, Wu, bu, n_nodes, nb_u);

    capture_align_kernel<<<1, 32>>>();                               // launch 3

    edge_kernel<<<n_seg / 2, 320>>>(natt, edges, edges_y, rel_t,     // launch 4
                                    ws, fb, ow, (float*)d_out, n_nodes);
}